// round 10
// baseline (speedup 1.0000x reference)
#include <cuda_runtime.h>
#include <math.h>

#define MARGIN 0.2f
#define EPS_V  1e-6f
#define ENC(i) (0x7FFFFFFF - (i))
#define MAXG   4096

// Zero-init at load; finalize_kernel resets prep tables each run so every
// graph replay sees identical initial state. Partials are overwritten fully.
__device__ int    g_first_enc[256];   // 0 = absent; else ENC(first idx)
__device__ int    g_mfirst_enc;       // 0 = all labels identical
__device__ float2 g_part[MAXG];       // per-block (sum, count)

// ---------------------------------------------------------------------------
// K1: multi-block prep. Global atomics spread across L2 (no 1-SM bottleneck).
// ---------------------------------------------------------------------------
__global__ void __launch_bounds__(256) prep_kernel(const int* __restrict__ label, int B) {
    const int i    = blockIdx.x * 256 + threadIdx.x;
    const int lane = threadIdx.x & 31;
    const int l0   = __ldg(&label[0]);

    const int lab = (i < B) ? __ldg(&label[i]) : l0;
    if (i < B)
        atomicMax(&g_first_enc[lab & 255], ENC(i));

    unsigned m = __ballot_sync(0xffffffffu, (i < B) && (lab != l0));
    if (lane == 0 && m) {
        int j = (i - lane) + __ffs(m) - 1;
        atomicMax(&g_mfirst_enc, ENC(j));
    }
}

// ---------------------------------------------------------------------------
// K2: one warp per row. a-row prefetched into registers BEFORE the grid
// dependency sync (overlaps prep; 8 back-to-back LDG.128 -> deep MLP).
// Tail: ONE plain float2 store per block. No atomics, no fences -> no L1
// flush, no single-address atomic drain.
// ---------------------------------------------------------------------------
__global__ void __launch_bounds__(256) triplet_kernel(const float* __restrict__ z,
                                                      const int* __restrict__ label,
                                                      const int* __restrict__ zidx,
                                                      int B, int C, int k) {
    const int warp = threadIdx.x >> 5;
    const int lane = threadIdx.x & 31;
    const int i = blockIdx.x * 8 + warp;

    // ---- independent of prep: prefetch a-row + scalars ----
    float4 av[8];
    const bool fast = (C == 1024) && (i < B);
    const float4* a = (const float4*)(z + (size_t)((i < B) ? i : 0) * C);
    if (fast) {
        #pragma unroll
        for (int u = 0; u < 8; u++)
            av[u] = a[lane + (u << 5)];
    }
    const int lab_i = (i < B) ? __ldg(&label[i]) : 0;
    const int l0    = __ldg(&label[0]);
    const int idx_i = (i < B) ? __ldg(&zidx[i]) : 0;

    // ---- wait for prep ----
    cudaGridDependencySynchronize();

    float per = 0.0f;
    float vld = 0.0f;

    if (i < B) {
        const bool allsame = (g_mfirst_enc == 0);
        int pos = -1, neg = -1;

        if (!allsame) {
            const int f = 0x7FFFFFFF - g_first_enc[lab_i & 255];
            if (f != i) {
                pos = f;
                if (__ldg(&zidx[f]) == idx_i) pos = -1;   // degenerate zidx dup
            }
            if (pos < 0) {
                // i is the first occurrence: scan forward for the 2nd (rare)
                for (int base = i + 1; base < B; base += 32) {
                    int j = base + lane;
                    bool ok = false;
                    if (j < B)
                        ok = (__ldg(&label[j]) == lab_i) && (__ldg(&zidx[j]) != idx_i);
                    unsigned m = __ballot_sync(0xffffffffu, ok);
                    if (m) { pos = base + __ffs(m) - 1; break; }
                }
            }
            neg = (lab_i != l0) ? 0 : (0x7FFFFFFF - g_mfirst_enc);
        } else {
            // all labels equal: effective labels are -1 for j<k, l0 otherwise
            if (i < k) { pos = (i == 0) ? 1 : 0;       neg = k; }
            else       { pos = (i == k) ? (k + 1) : k; neg = 0; }
            if (pos >= B || neg >= B || k < 2) { pos = -1; }
        }

        if (pos >= 0 && pos < B && neg >= 0 && neg < B) {
            const float4* p = (const float4*)(z + (size_t)pos * C);
            const float4* n = (const float4*)(z + (size_t)neg * C);
            float sap = 0.0f, san = 0.0f;
            if (fast) {
                #pragma unroll
                for (int u = 0; u < 8; u++) {
                    const int v = lane + (u << 5);
                    float4 pv = __ldg(&p[v]);
                    float4 nv = __ldg(&n[v]);
                    float d;
                    d = av[u].x - pv.x + EPS_V; sap = fmaf(d, d, sap);
                    d = av[u].y - pv.y + EPS_V; sap = fmaf(d, d, sap);
                    d = av[u].z - pv.z + EPS_V; sap = fmaf(d, d, sap);
                    d = av[u].w - pv.w + EPS_V; sap = fmaf(d, d, sap);
                    d = av[u].x - nv.x + EPS_V; san = fmaf(d, d, san);
                    d = av[u].y - nv.y + EPS_V; san = fmaf(d, d, san);
                    d = av[u].z - nv.z + EPS_V; san = fmaf(d, d, san);
                    d = av[u].w - nv.w + EPS_V; san = fmaf(d, d, san);
                }
            } else {
                const int nvec = C >> 2;
                for (int v = lane; v < nvec; v += 32) {
                    float4 avv = a[v];
                    float4 pv = __ldg(&p[v]);
                    float4 nv = __ldg(&n[v]);
                    float d;
                    d = avv.x - pv.x + EPS_V; sap = fmaf(d, d, sap);
                    d = avv.y - pv.y + EPS_V; sap = fmaf(d, d, sap);
                    d = avv.z - pv.z + EPS_V; sap = fmaf(d, d, sap);
                    d = avv.w - pv.w + EPS_V; sap = fmaf(d, d, sap);
                    d = avv.x - nv.x + EPS_V; san = fmaf(d, d, san);
                    d = avv.y - nv.y + EPS_V; san = fmaf(d, d, san);
                    d = avv.z - nv.z + EPS_V; san = fmaf(d, d, san);
                    d = avv.w - nv.w + EPS_V; san = fmaf(d, d, san);
                }
            }
            #pragma unroll
            for (int o = 16; o > 0; o >>= 1) {
                sap += __shfl_xor_sync(0xffffffffu, sap, o);
                san += __shfl_xor_sync(0xffffffffu, san, o);
            }
            per = fmaxf(sqrtf(sap) - sqrtf(san) + MARGIN, 0.0f);
            vld = 1.0f;
        }
    }

    // ---- tail: one plain store per block (deterministic in-block order) ----
    __shared__ float s_s[8];
    __shared__ float s_c[8];
    if (lane == 0) { s_s[warp] = per; s_c[warp] = vld; }
    __syncthreads();
    if (threadIdx.x == 0) {
        float s = 0.0f, c = 0.0f;
        #pragma unroll
        for (int w = 0; w < 8; w++) { s += s_s[w]; c += s_c[w]; }
        g_part[blockIdx.x] = make_float2(s, c);
    }
}

// ---------------------------------------------------------------------------
// K3: deterministic reduction of per-block partials; also resets prep tables
// for the next graph replay. PDL hides its launch/wait.
// ---------------------------------------------------------------------------
__global__ void __launch_bounds__(256) finalize_kernel(float* __restrict__ out,
                                                       int nblocks) {
    cudaGridDependencySynchronize();
    __shared__ float s_s[256];
    __shared__ float s_c[256];
    const int tid = threadIdx.x;
    float s = 0.0f, c = 0.0f;
    for (int b = tid; b < nblocks; b += 256) {
        float2 t = g_part[b];
        s += t.x; c += t.y;
    }
    s_s[tid] = s; s_c[tid] = c;
    __syncthreads();
    #pragma unroll
    for (int o = 128; o > 0; o >>= 1) {
        if (tid < o) { s_s[tid] += s_s[tid + o]; s_c[tid] += s_c[tid + o]; }
        __syncthreads();
    }
    if (tid == 0) {
        out[0] = (s_c[0] > 0.0f) ? (s_s[0] / s_c[0]) : 0.0f;
        g_mfirst_enc = 0;
    }
    g_first_enc[tid & 255] = 0;   // reset prep table for next replay
}

extern "C" void kernel_launch(void* const* d_in, const int* in_sizes, int n_in,
                              void* d_out, int out_size) {
    const int* z_label = (const int*)d_in[0];
    const int* z_idx   = (const int*)d_in[1];
    const float* z     = (const float*)d_in[2];
    float* out = (float*)d_out;

    const int B = in_sizes[0];
    const int C = in_sizes[2] / B;
    int k = (int)((double)B * 0.01);
    if (k < 2) k = 2;

    const int prep_blocks = (B + 255) / 256;
    prep_kernel<<<prep_blocks, 256>>>(z_label, B);

    int nblocks = (B + 7) / 8;
    if (nblocks > MAXG) nblocks = MAXG;
    {
        cudaLaunchConfig_t cfg = {};
        cfg.gridDim = dim3(nblocks);
        cfg.blockDim = dim3(256);
        cfg.dynamicSmemBytes = 0;
        cfg.stream = 0;
        cudaLaunchAttribute at[1];
        at[0].id = cudaLaunchAttributeProgrammaticStreamSerialization;
        at[0].val.programmaticStreamSerializationAllowed = 1;
        cfg.attrs = at;
        cfg.numAttrs = 1;
        cudaLaunchKernelEx(&cfg, triplet_kernel, z, z_label, z_idx, B, C, k);
    }
    {
        cudaLaunchConfig_t cfg = {};
        cfg.gridDim = dim3(1);
        cfg.blockDim = dim3(256);
        cfg.dynamicSmemBytes = 0;
        cfg.stream = 0;
        cudaLaunchAttribute at[1];
        at[0].id = cudaLaunchAttributeProgrammaticStreamSerialization;
        at[0].val.programmaticStreamSerializationAllowed = 1;
        cfg.attrs = at;
        cfg.numAttrs = 1;
        cudaLaunchKernelEx(&cfg, finalize_kernel, out, nblocks);
    }
}

// round 11
// speedup vs baseline: 1.5209x; 1.5209x over previous
#include <cuda_runtime.h>
#include <math.h>

#define MARGIN 0.2f
#define EPS_V  1e-6f

// Packed accumulator: bits[0:38) sum_q (fixed-point 2^16),
//                     bits[38:52) valid count, bits[52:64) done-block count.
#define CNT_SHIFT  38
#define DONE_SHIFT 52
#define SUM_MASK   ((1ull << CNT_SHIFT) - 1ull)
#define CNT_MASK   ((1ull << (DONE_SHIFT - CNT_SHIFT)) - 1ull)
#define FIXP       65536.0

// Only global state: zero-init at load; last block resets it each run so
// every graph replay sees identical initial state.
__device__ unsigned long long g_acc;

// ---------------------------------------------------------------------------
// Warp-collective: first j with label[j] != l0 (or -1 if none -> all same).
// int4 loads: 128 labels per step; expected ~1 step for random labels.
// ---------------------------------------------------------------------------
__device__ __forceinline__ int warp_find_first_diff(const int* __restrict__ label,
                                                    int B, int lane, int l0) {
    for (int base = 0; base < B; base += 128) {
        const int j0 = base + (lane << 2);
        unsigned sub = 0u;
        if (j0 + 3 < B) {
            int4 lv = *(const int4*)(label + j0);
            sub = (lv.x != l0 ? 1u : 0u) | (lv.y != l0 ? 2u : 0u)
                | (lv.z != l0 ? 4u : 0u) | (lv.w != l0 ? 8u : 0u);
        } else {
            #pragma unroll
            for (int t = 0; t < 4; t++) {
                int j = j0 + t;
                if (j < B && label[j] != l0) sub |= 1u << t;
            }
        }
        unsigned act = __ballot_sync(0xffffffffu, sub != 0u);
        if (act) {
            int src = __ffs(act) - 1;
            unsigned ssub = __shfl_sync(0xffffffffu, sub, src);
            return base + (src << 2) + (__ffs(ssub) - 1);
        }
    }
    return -1;
}

// ---------------------------------------------------------------------------
// Warp-collective: first j with label[j]==lab_i && zidx[j]!=idx_i (or -1).
// Expected ~2 steps (label frequency ~1/256). zidx rejects are rare.
// ---------------------------------------------------------------------------
__device__ __forceinline__ int warp_find_pos(const int* __restrict__ label,
                                             const int* __restrict__ zidx,
                                             int B, int lane, int lab_i, int idx_i) {
    for (int base = 0; base < B; base += 128) {
        const int j0 = base + (lane << 2);
        unsigned sub = 0u;
        if (j0 + 3 < B) {
            int4 lv = *(const int4*)(label + j0);
            sub = (lv.x == lab_i ? 1u : 0u) | (lv.y == lab_i ? 2u : 0u)
                | (lv.z == lab_i ? 4u : 0u) | (lv.w == lab_i ? 8u : 0u);
        } else {
            #pragma unroll
            for (int t = 0; t < 4; t++) {
                int j = j0 + t;
                if (j < B && label[j] == lab_i) sub |= 1u << t;
            }
        }
        while (true) {
            unsigned act = __ballot_sync(0xffffffffu, sub != 0u);
            if (!act) break;
            int src = __ffs(act) - 1;
            unsigned ssub = __shfl_sync(0xffffffffu, sub, src);
            int j = base + (src << 2) + (__ffs(ssub) - 1);
            if (__ldg(&zidx[j]) != idx_i) return j;   // broadcast load (same j)
            if (lane == src) sub &= (sub - 1u);       // drop rejected candidate
        }
    }
    return -1;
}

// ---------------------------------------------------------------------------
// Single fused kernel: one warp per row. a-row prefetched first (8
// back-to-back LDG.128 -> deep DRAM MLP); mining scans run while those loads
// are in flight. Tail = one packed relaxed atomicAdd per block (no fences ->
// no L1 flush); last block writes the scalar and resets state.
// ---------------------------------------------------------------------------
__global__ void __launch_bounds__(256) triplet_kernel(const float* __restrict__ z,
                                                      const int* __restrict__ label,
                                                      const int* __restrict__ zidx,
                                                      float* __restrict__ out,
                                                      int B, int C, int k,
                                                      unsigned int nblocks) {
    const int warp = threadIdx.x >> 5;
    const int lane = threadIdx.x & 31;
    const int i = blockIdx.x * 8 + warp;

    float per = 0.0f;
    float vld = 0.0f;

    if (i < B) {
        // ---- prefetch a-row (the only DRAM-streaming operand) ----
        float4 av[8];
        const bool fast = (C == 1024);
        const float4* a = (const float4*)(z + (size_t)i * C);
        if (fast) {
            #pragma unroll
            for (int u = 0; u < 8; u++)
                av[u] = a[lane + (u << 5)];
        }

        const int lab_i = __ldg(&label[i]);
        const int l0    = __ldg(&label[0]);
        const int idx_i = __ldg(&zidx[i]);

        // ---- mining (overlaps the in-flight a-row loads) ----
        int pos = -1, neg = -1;
        bool closed = false;
        if (lab_i != l0) {
            neg = 0;                                   // label[0] differs
        } else {
            neg = warp_find_first_diff(label, B, lane, l0);
            if (neg < 0) closed = true;                // all labels identical
        }

        if (!closed) {
            pos = warp_find_pos(label, zidx, B, lane, lab_i, idx_i);
        } else {
            // all-same: effective labels are -1 for j<k, l0 otherwise (k>=2)
            if (i < k) { pos = (i == 0) ? 1 : 0;       neg = k; }
            else       { pos = (i == k) ? (k + 1) : k; neg = 0; }
            if (pos >= B || neg >= B || k < 2) pos = -1;
        }

        if (pos >= 0 && neg >= 0) {
            const float4* p = (const float4*)(z + (size_t)pos * C);
            const float4* n = (const float4*)(z + (size_t)neg * C);
            float sap = 0.0f, san = 0.0f;
            if (fast) {
                #pragma unroll
                for (int u = 0; u < 8; u++) {
                    const int v = lane + (u << 5);
                    float4 pv = __ldg(&p[v]);
                    float4 nv = __ldg(&n[v]);
                    float d;
                    d = av[u].x - pv.x + EPS_V; sap = fmaf(d, d, sap);
                    d = av[u].y - pv.y + EPS_V; sap = fmaf(d, d, sap);
                    d = av[u].z - pv.z + EPS_V; sap = fmaf(d, d, sap);
                    d = av[u].w - pv.w + EPS_V; sap = fmaf(d, d, sap);
                    d = av[u].x - nv.x + EPS_V; san = fmaf(d, d, san);
                    d = av[u].y - nv.y + EPS_V; san = fmaf(d, d, san);
                    d = av[u].z - nv.z + EPS_V; san = fmaf(d, d, san);
                    d = av[u].w - nv.w + EPS_V; san = fmaf(d, d, san);
                }
            } else {
                const int nvec = C >> 2;
                for (int v = lane; v < nvec; v += 32) {
                    float4 avv = a[v];
                    float4 pv = __ldg(&p[v]);
                    float4 nv = __ldg(&n[v]);
                    float d;
                    d = avv.x - pv.x + EPS_V; sap = fmaf(d, d, sap);
                    d = avv.y - pv.y + EPS_V; sap = fmaf(d, d, sap);
                    d = avv.z - pv.z + EPS_V; sap = fmaf(d, d, sap);
                    d = avv.w - pv.w + EPS_V; sap = fmaf(d, d, sap);
                    d = avv.x - nv.x + EPS_V; san = fmaf(d, d, san);
                    d = avv.y - nv.y + EPS_V; san = fmaf(d, d, san);
                    d = avv.z - nv.z + EPS_V; san = fmaf(d, d, san);
                    d = avv.w - nv.w + EPS_V; san = fmaf(d, d, san);
                }
            }
            #pragma unroll
            for (int o = 16; o > 0; o >>= 1) {
                sap += __shfl_xor_sync(0xffffffffu, sap, o);
                san += __shfl_xor_sync(0xffffffffu, san, o);
            }
            per = fmaxf(sqrtf(sap) - sqrtf(san) + MARGIN, 0.0f);
            vld = 1.0f;
        }
    }

    // ---- single-atomic deterministic tail ----
    __shared__ float s_s[8];
    __shared__ float s_c[8];
    if (lane == 0) { s_s[warp] = per; s_c[warp] = vld; }
    __syncthreads();
    if (threadIdx.x == 0) {
        double bsum = 0.0; unsigned int c = 0u;
        #pragma unroll
        for (int w = 0; w < 8; w++) { bsum += (double)s_s[w]; c += (unsigned int)s_c[w]; }
        unsigned long long q = (unsigned long long)(bsum * FIXP + 0.5);
        unsigned long long val = q
                               | ((unsigned long long)c << CNT_SHIFT)
                               | (1ull << DONE_SHIFT);
        unsigned long long old = atomicAdd(&g_acc, val);   // relaxed, no fence
        if ((old >> DONE_SHIFT) == (unsigned long long)(nblocks - 1u)) {
            unsigned long long t = old + val;
            unsigned long long sq = t & SUM_MASK;
            unsigned int cc = (unsigned int)((t >> CNT_SHIFT) & CNT_MASK);
            out[0] = (cc > 0u) ? (float)(((double)sq / FIXP) / (double)cc) : 0.0f;
            g_acc = 0ull;   // reset for next graph replay
        }
    }
}

extern "C" void kernel_launch(void* const* d_in, const int* in_sizes, int n_in,
                              void* d_out, int out_size) {
    const int* z_label = (const int*)d_in[0];
    const int* z_idx   = (const int*)d_in[1];
    const float* z     = (const float*)d_in[2];
    float* out = (float*)d_out;

    const int B = in_sizes[0];
    const int C = in_sizes[2] / B;
    int k = (int)((double)B * 0.01);
    if (k < 2) k = 2;

    const unsigned int nblocks = (unsigned int)((B + 7) / 8);
    triplet_kernel<<<nblocks, 256>>>(z, z_label, z_idx, out, B, C, k, nblocks);
}